// round 1
// baseline (speedup 1.0000x reference)
#include <cuda_runtime.h>

#define NN 8192
#define DD 64
#define MAXDEG 16
#define KK 8
#define LL 17            // MAXDEG + 1
#define DIN 128          // D * EXPAND
#define EE (NN*KK)
#define EPS 1e-5f

// ---------------- device scratch (allocation-free) ----------------
__device__ float g_hflat[NN*MAXDEG*DD];   // sorted mailbox, flattened [N,1024]
__device__ float g_hinput[NN*LL*DD];      // [N,17,64]
__device__ float g_y[NN*LL*DD];           // [N,17,64]
__device__ float g_bnsum[DD];
__device__ float g_bnsq[DD];

__device__ __forceinline__ float sigm(float x) { return 1.f/(1.f+__expf(-x)); }

// ---------------- K0: zero BN accumulators (graph replays!) ----------------
__global__ void kz() {
    int t = threadIdx.x;
    if (t < DD) { g_bnsum[t] = 0.f; g_bnsq[t] = 0.f; }
}

// ---------------- K1: message + mailbox rank-sort ----------------
// block = 4 nodes x 64 lanes
__global__ void k1(const float* __restrict__ hs, const float* __restrict__ hs_e,
                   const float* __restrict__ degree, const float* __restrict__ noise) {
    int n = blockIdx.x*4 + (threadIdx.x >> 6);
    int d = threadIdx.x & 63;
    float h = hs[n*DD + d];
    float deg = __ldg(&degree[n]);
    float sc[KK];
#pragma unroll
    for (int k = 0; k < KK; k++) sc[k] = deg + __ldg(&noise[n*KK + k]);
#pragma unroll
    for (int k = 0; k < KK; k++) {
        float e = hs_e[(n*KK + k)*DD + d];
        float m = h * sigm(e);
        int r = 0;
#pragma unroll
        for (int j = 0; j < KK; j++)
            r += (sc[j] < sc[k]) || (sc[j] == sc[k] && j < k);   // stable rank
        g_hflat[n*(MAXDEG*DD) + r*DD + d] = m;
    }
#pragma unroll
    for (int j = KK; j < MAXDEG; j++)
        g_hflat[n*(MAXDEG*DD) + j*DD + d] = 0.f;
}

// ---------------- K2: (A+I) spmm gather + build h_input ----------------
// block = 1 node, 256 threads (each handles one float4 of the 1024-wide row)
__global__ void k2(const float* __restrict__ hs, const int* __restrict__ src) {
    int n = blockIdx.x;
    int t = threadIdx.x;
    if (t < DD) g_hinput[n*(LL*DD) + t] = hs[n*DD + t];   // slot 0 = hs
    float4 a = ((const float4*)(g_hflat + n*(MAXDEG*DD)))[t];
#pragma unroll
    for (int k = 0; k < KK; k++) {
        int s = __ldg(&src[n*KK + k]);
        float4 v = ((const float4*)(g_hflat + s*(MAXDEG*DD)))[t];
        a.x += v.x; a.y += v.y; a.z += v.z; a.w += v.w;
    }
    ((float4*)(g_hinput + n*(LL*DD) + DD))[t] = a;        // slots 1..16
}

// ---------------- K3: GatedCNN + RMSNorm + residual + BN partials ----------------
// persistent: 148 blocks x 256 threads, 4 nodes per block, 64 threads per node
__global__ void __launch_bounds__(256, 1)
k3(const float* __restrict__ fc1w, const float* __restrict__ fc1b,
   const float* __restrict__ convw, const float* __restrict__ convb,
   const float* __restrict__ fc2w, const float* __restrict__ fc2b,
   const float* __restrict__ rmsw) {
    extern __shared__ float sm[];
    float* w1t = sm;                     // [64][256]  fc1_w transposed
    float* w2t = sm + 16384;             // [128][64]  fc2_w transposed
    float* hsm = w2t + 8192;             // [4][17*64] h_input tiles
    float* gz  = hsm + 4*LL*DD;          // [4][17*128] silu(z) then gated
    float* ob  = gz  + 4*LL*DIN;         // [4][17*64] fc2 out
    float* rr  = ob  + 4*LL*DD;          // [4][17] rms factors

    int t = threadIdx.x;
    for (int i = t; i < 256*64; i += 256) { int c = i >> 6, k = i & 63; w1t[k*256 + c] = fc1w[i]; }
    for (int i = t; i < 64*128; i += 256) { int dd = i >> 7, c = i & 127; w2t[c*64 + dd] = fc2w[i]; }

    int g = t >> 6, u = t & 63;

    float b1[4];
#pragma unroll
    for (int i = 0; i < 4; i++) b1[i] = __ldg(&fc1b[u*4 + i]);
    float cw[4][4], cb[4];
    if (u < 32) {
#pragma unroll
        for (int i = 0; i < 4; i++) {
            int c = u*4 + i;
#pragma unroll
            for (int tt = 0; tt < 4; tt++) cw[i][tt] = __ldg(&convw[c*4 + tt]);
            cb[i] = __ldg(&convb[c]);
        }
    }
    float b2 = __ldg(&fc2b[u]);
    float rw = __ldg(&rmsw[u]);
    float bsum = 0.f, bsq = 0.f;
    __syncthreads();

    for (int grp = blockIdx.x; grp < NN/4; grp += gridDim.x) {
        // load 4 nodes' h_input
        {
            const float4* s4 = (const float4*)(g_hinput + (size_t)grp*4*(LL*DD));
            float4* d4 = (float4*)hsm;
            for (int i = t; i < 4*LL*DD/4; i += 256) d4[i] = s4[i];
        }
        __syncthreads();

        const float* hrow = hsm + g*(LL*DD);

        // ---- fc1: acc[l][i] = h_input[l,:] . fc1_w[c,:], c = u*4+i ----
        float acc[LL][4];
#pragma unroll
        for (int l = 0; l < LL; l++) { acc[l][0] = 0; acc[l][1] = 0; acc[l][2] = 0; acc[l][3] = 0; }
#pragma unroll 1
        for (int k4 = 0; k4 < 16; k4++) {
            float4 wa = *(const float4*)&w1t[(k4*4+0)*256 + u*4];
            float4 wb = *(const float4*)&w1t[(k4*4+1)*256 + u*4];
            float4 wc = *(const float4*)&w1t[(k4*4+2)*256 + u*4];
            float4 wd = *(const float4*)&w1t[(k4*4+3)*256 + u*4];
#pragma unroll
            for (int l = 0; l < LL; l++) {
                float4 h4 = *(const float4*)&hrow[l*DD + k4*4];
                acc[l][0] += h4.x*wa.x + h4.y*wb.x + h4.z*wc.x + h4.w*wd.x;
                acc[l][1] += h4.x*wa.y + h4.y*wb.y + h4.z*wc.y + h4.w*wd.y;
                acc[l][2] += h4.x*wa.z + h4.y*wb.z + h4.z*wc.z + h4.w*wd.z;
                acc[l][3] += h4.x*wa.w + h4.y*wb.w + h4.z*wc.w + h4.w*wd.w;
            }
        }
#pragma unroll
        for (int l = 0; l < LL; l++)
#pragma unroll
            for (int i = 0; i < 4; i++) acc[l][i] += b1[i];

        // z-threads (channels 128..255): silu(z) -> gz
        if (u >= 32) {
#pragma unroll
            for (int l = 0; l < LL; l++)
#pragma unroll
                for (int i = 0; i < 4; i++) {
                    float v = acc[l][i];
                    gz[g*(LL*DIN) + l*DIN + (u*4 + i - DIN)] = v * sigm(v);
                }
        }
        __syncthreads();

        // x-threads (channels 0..127): causal depthwise conv + gate (in place)
        if (u < 32) {
#pragma unroll
            for (int l = 0; l < LL; l++) {
#pragma unroll
                for (int i = 0; i < 4; i++) {
                    float xc = cb[i];
#pragma unroll
                    for (int tt = 0; tt < 4; tt++) {
                        int ls = l - 3 + tt;
                        if (ls >= 0) xc += acc[ls][i] * cw[i][tt];
                    }
                    float sx = xc * sigm(xc);
                    int idx = g*(LL*DIN) + l*DIN + u*4 + i;
                    gz[idx] = sx * gz[idx];
                }
            }
        }
        __syncthreads();

        // ---- fc2: out[l][d] = gated[l,:] . fc2_w[d,:], d = u ----
        float acc2[LL];
#pragma unroll
        for (int l = 0; l < LL; l++) acc2[l] = 0.f;
        const float* grow = gz + g*(LL*DIN);
#pragma unroll 1
        for (int c4 = 0; c4 < 32; c4++) {
            float wa = w2t[(c4*4+0)*64 + u];
            float wb = w2t[(c4*4+1)*64 + u];
            float wc = w2t[(c4*4+2)*64 + u];
            float wd = w2t[(c4*4+3)*64 + u];
#pragma unroll
            for (int l = 0; l < LL; l++) {
                float4 g4 = *(const float4*)&grow[l*DIN + c4*4];
                acc2[l] += g4.x*wa + g4.y*wb + g4.z*wc + g4.w*wd;
            }
        }
#pragma unroll
        for (int l = 0; l < LL; l++) ob[g*(LL*DD) + l*DD + u] = acc2[l] + b2;
        __syncthreads();

        // rms factors: 68 rows, staggered to dodge bank conflicts
        if (t < 68) {
            int gg = t / LL, ll = t % LL;
            const float* r = ob + gg*(LL*DD) + ll*DD;
            float s = 0.f;
            for (int dd = 0; dd < DD; dd++) { float v = r[(dd + t) & 63]; s += v*v; }
            rr[t] = rsqrtf(s * (1.f/DD) + EPS);
        }
        __syncthreads();

        // y = rmsnorm(out)*rms_w + h_input; store + BN partials
        int node = grp*4 + g;
        float* yrow = g_y + (size_t)node*(LL*DD);
#pragma unroll
        for (int l = 0; l < LL; l++) {
            float v = ob[g*(LL*DD) + l*DD + u] * rr[g*LL + l] * rw + hrow[l*DD + u];
            yrow[l*DD + u] = v;
            bsum += v; bsq += v*v;
        }
        __syncthreads();   // before next iteration overwrites hsm/gz/ob
    }
    atomicAdd(&g_bnsum[u], bsum);
    atomicAdd(&g_bnsq[u], bsq);
}

// ---------------- K5: BN apply + ReLU6 + L-aggregation + residual ----------------
__global__ void k5(const float* __restrict__ hs, const float* __restrict__ gamma,
                   const float* __restrict__ beta, const float* __restrict__ aggw,
                   const float* __restrict__ aggb, float* __restrict__ out) {
    int idx = blockIdx.x*256 + threadIdx.x;
    int d = idx & 63;
    float cnt = (float)(NN*LL);
    float mean = g_bnsum[d] / cnt;
    float var  = g_bnsq[d] / cnt - mean*mean;
    float is = rsqrtf(var + EPS);
    float ga = __ldg(&gamma[d]) * is;
    float be = __ldg(&beta[d]) - mean * ga;
    const float* yrow = g_y + (size_t)(idx >> 6)*(LL*DD);
    float s = __ldg(&aggb[0]);
#pragma unroll
    for (int l = 0; l < LL; l++) {
        float v = yrow[l*DD + d] * ga + be;
        v = fminf(fmaxf(v, 0.f), 6.f);
        s += v * __ldg(&aggw[l]);
    }
    out[idx] = s + hs[idx];
}

// ---------------- host ----------------
extern "C" void kernel_launch(void* const* d_in, const int* in_sizes, int n_in,
                              void* d_out, int out_size) {
    const float* hs     = (const float*)d_in[0];
    const float* hs_e   = (const float*)d_in[1];
    const float* degree = (const float*)d_in[2];
    const float* noise  = (const float*)d_in[3];
    const float* fc1w   = (const float*)d_in[4];
    const float* fc1b   = (const float*)d_in[5];
    const float* convw  = (const float*)d_in[6];
    const float* convb  = (const float*)d_in[7];
    const float* fc2w   = (const float*)d_in[8];
    const float* fc2b   = (const float*)d_in[9];
    const float* rmsw   = (const float*)d_in[10];
    const float* gamma  = (const float*)d_in[11];
    const float* beta   = (const float*)d_in[12];
    const float* aggw   = (const float*)d_in[13];
    const float* aggb   = (const float*)d_in[14];
    const int*   src    = (const int*)d_in[15];
    // d_in[16] = dst: structurally arange(E)//K, unused
    float* out = (float*)d_out;

    const int smem3 = (16384 + 8192 + 4*LL*DD + 4*LL*DIN + 4*LL*DD + 4*LL) * 4;
    cudaFuncSetAttribute(k3, cudaFuncAttributeMaxDynamicSharedMemorySize, smem3);

    kz<<<1, 64>>>();
    k1<<<NN/4, 256>>>(hs, hs_e, degree, noise);
    k2<<<NN, 256>>>(hs, src);
    k3<<<148, 256, smem3>>>(fc1w, fc1b, convw, convb, fc2w, fc2b, rmsw);
    k5<<<NN*DD/256, 256>>>(hs, gamma, beta, aggw, aggb, out);
}

// round 2
// speedup vs baseline: 1.1529x; 1.1529x over previous
#include <cuda_runtime.h>

#define NN 8192
#define DD 64
#define MAXDEG 16
#define KK 8
#define LL 17            // MAXDEG + 1
#define DIN 128          // D * EXPAND
#define EPS 1e-5f

// ---------------- device scratch (allocation-free) ----------------
__device__ float g_hflat[NN*MAXDEG*DD];   // sorted mailbox, flattened [N,1024]
__device__ float g_hinput[NN*LL*DD];      // [N,17,64]
__device__ float g_y[NN*LL*DD];           // [N,17,64]
__device__ float g_bnsum[DD];
__device__ float g_bnsq[DD];

__device__ __forceinline__ float sigm(float x) { return 1.f/(1.f+__expf(-x)); }

// ---------------- K0: zero BN accumulators (graph replays!) ----------------
__global__ void kz() {
    int t = threadIdx.x;
    if (t < DD) { g_bnsum[t] = 0.f; g_bnsq[t] = 0.f; }
}

// ---------------- K1: message + mailbox rank-sort ----------------
__global__ void k1(const float* __restrict__ hs, const float* __restrict__ hs_e,
                   const float* __restrict__ degree, const float* __restrict__ noise) {
    int n = blockIdx.x*4 + (threadIdx.x >> 6);
    int d = threadIdx.x & 63;
    float h = hs[n*DD + d];
    float deg = __ldg(&degree[n]);
    float sc[KK];
#pragma unroll
    for (int k = 0; k < KK; k++) sc[k] = deg + __ldg(&noise[n*KK + k]);
#pragma unroll
    for (int k = 0; k < KK; k++) {
        float e = hs_e[(n*KK + k)*DD + d];
        float m = h * sigm(e);
        int r = 0;
#pragma unroll
        for (int j = 0; j < KK; j++)
            r += (sc[j] < sc[k]) || (sc[j] == sc[k] && j < k);   // stable rank
        g_hflat[n*(MAXDEG*DD) + r*DD + d] = m;
    }
#pragma unroll
    for (int j = KK; j < MAXDEG; j++)
        g_hflat[n*(MAXDEG*DD) + j*DD + d] = 0.f;
}

// ---------------- K2: (A+I) spmm gather + build h_input ----------------
__global__ void k2(const float* __restrict__ hs, const int* __restrict__ src) {
    int n = blockIdx.x;
    int t = threadIdx.x;
    if (t < DD) g_hinput[n*(LL*DD) + t] = hs[n*DD + t];   // slot 0 = hs
    float4 a = ((const float4*)(g_hflat + n*(MAXDEG*DD)))[t];
#pragma unroll
    for (int k = 0; k < KK; k++) {
        int s = __ldg(&src[n*KK + k]);
        float4 v = ((const float4*)(g_hflat + s*(MAXDEG*DD)))[t];
        a.x += v.x; a.y += v.y; a.z += v.z; a.w += v.w;
    }
    ((float4*)(g_hinput + n*(LL*DD) + DD))[t] = a;        // slots 1..16
}

// ---------------- K3: GatedCNN + RMSNorm + residual + BN partials ----------------
// persistent: 148 blocks x 512 threads, 4 nodes/block, 128 threads/node
// fc1: thread owns 2 channels x 17 rows. fc2: thread owns 1 channel x 8/9 rows.
__global__ void __launch_bounds__(512, 1)
k3(const float* __restrict__ fc1w, const float* __restrict__ fc1b,
   const float* __restrict__ convw, const float* __restrict__ convb,
   const float* __restrict__ fc2w, const float* __restrict__ fc2b,
   const float* __restrict__ rmsw) {
    extern __shared__ float sm[];
    float* w1t = sm;                     // [64][256]  fc1_w transposed (k-major)
    float* w2t = sm + 16384;             // [128][64]  fc2_w transposed (c-major)
    float* hsm = w2t + 8192;             // [4][17*64]
    float* gz  = hsm + 4*LL*DD;          // [4][17*128]
    float* ob  = gz  + 4*LL*DIN;         // [4][17*64]
    float* rr  = ob  + 4*LL*DD;          // [4*17]

    int t = threadIdx.x;
    for (int i = t; i < 256*64; i += 512) { int c = i >> 6, k = i & 63; w1t[k*256 + c] = fc1w[i]; }
    for (int i = t; i < 64*128; i += 512) { int dd = i >> 7, c = i & 127; w2t[c*64 + dd] = fc2w[i]; }

    int g = t >> 7;          // node within block (0..3)
    int u = t & 127;         // thread within node
    int d = u & 63;          // fc2 output channel
    int lh = u >> 6;         // fc2/y L-half
    int lbase = lh * 9;      // lh=0: rows 0..8, lh=1: rows 9..16

    float b1x = __ldg(&fc1b[u*2]), b1y = __ldg(&fc1b[u*2+1]);
    float cw0[4], cw1[4], cb0 = 0.f, cb1 = 0.f;
    if (u < 64) {
#pragma unroll
        for (int tt = 0; tt < 4; tt++) {
            cw0[tt] = __ldg(&convw[(u*2+0)*4 + tt]);
            cw1[tt] = __ldg(&convw[(u*2+1)*4 + tt]);
        }
        cb0 = __ldg(&convb[u*2]); cb1 = __ldg(&convb[u*2+1]);
    }
    float b2 = __ldg(&fc2b[d]);
    float rw = __ldg(&rmsw[d]);
    float bsum = 0.f, bsq = 0.f;
    __syncthreads();

    for (int grp = blockIdx.x; grp < NN/4; grp += gridDim.x) {
        // stage 4 nodes' h_input
        {
            const float4* s4 = (const float4*)(g_hinput + (size_t)grp*4*(LL*DD));
            float4* d4 = (float4*)hsm;
            for (int i = t; i < 4*LL*DD/4; i += 512) d4[i] = s4[i];
        }
        __syncthreads();

        const float* hrow = hsm + g*(LL*DD);

        // ---- fc1: 2 channels (u*2, u*2+1) x 17 rows ----
        float ax[LL], ay[LL];
#pragma unroll
        for (int l = 0; l < LL; l++) { ax[l] = 0.f; ay[l] = 0.f; }
#pragma unroll 1
        for (int k4 = 0; k4 < 16; k4++) {
            float2 w0 = *(const float2*)&w1t[(k4*4+0)*256 + u*2];
            float2 w1 = *(const float2*)&w1t[(k4*4+1)*256 + u*2];
            float2 w2 = *(const float2*)&w1t[(k4*4+2)*256 + u*2];
            float2 w3 = *(const float2*)&w1t[(k4*4+3)*256 + u*2];
#pragma unroll
            for (int l = 0; l < LL; l++) {
                float4 h4 = *(const float4*)&hrow[l*DD + k4*4];
                ax[l] += h4.x*w0.x + h4.y*w1.x + h4.z*w2.x + h4.w*w3.x;
                ay[l] += h4.x*w0.y + h4.y*w1.y + h4.z*w2.y + h4.w*w3.y;
            }
        }
#pragma unroll
        for (int l = 0; l < LL; l++) { ax[l] += b1x; ay[l] += b1y; }

        // z half (channels 128..255): silu(z) -> gz
        if (u >= 64) {
            float* zr = gz + g*(LL*DIN) + (u - 64)*2;
#pragma unroll
            for (int l = 0; l < LL; l++) {
                float2 v; v.x = ax[l]*sigm(ax[l]); v.y = ay[l]*sigm(ay[l]);
                *(float2*)&zr[l*DIN] = v;
            }
        }
        __syncthreads();

        // x half (channels 0..127): causal depthwise conv + gate (in place)
        if (u < 64) {
            float* xr = gz + g*(LL*DIN) + u*2;
#pragma unroll
            for (int l = 0; l < LL; l++) {
                float x0 = cb0, x1 = cb1;
#pragma unroll
                for (int tt = 0; tt < 4; tt++) {
                    int ls = l - 3 + tt;
                    if (ls >= 0) { x0 += ax[ls]*cw0[tt]; x1 += ay[ls]*cw1[tt]; }
                }
                float2 zv = *(const float2*)&xr[l*DIN];
                float2 o; o.x = x0*sigm(x0)*zv.x; o.y = x1*sigm(x1)*zv.y;
                *(float2*)&xr[l*DIN] = o;
            }
        }
        __syncthreads();

        // ---- fc2: channel d, rows lbase..lbase+8 ----
        float acc2[9];
#pragma unroll
        for (int j = 0; j < 9; j++) acc2[j] = 0.f;
        const float* grow = gz + g*(LL*DIN);
#pragma unroll 1
        for (int c4 = 0; c4 < 32; c4++) {
            float wa = w2t[(c4*4+0)*64 + d];
            float wb = w2t[(c4*4+1)*64 + d];
            float wc = w2t[(c4*4+2)*64 + d];
            float wd = w2t[(c4*4+3)*64 + d];
#pragma unroll
            for (int j = 0; j < 9; j++) {
                int l = lbase + j;
                if (l < LL) {
                    float4 g4 = *(const float4*)&grow[l*DIN + c4*4];
                    acc2[j] += g4.x*wa + g4.y*wb + g4.z*wc + g4.w*wd;
                }
            }
        }
#pragma unroll
        for (int j = 0; j < 9; j++) {
            int l = lbase + j;
            if (l < LL) ob[g*(LL*DD) + l*DD + d] = acc2[j] + b2;
        }
        __syncthreads();

        // rms factors (68 rows, staggered reads to dodge conflicts)
        if (t < 68) {
            int gg = t / LL, ll = t % LL;
            const float* r = ob + gg*(LL*DD) + ll*DD;
            float s = 0.f;
            for (int dd = 0; dd < DD; dd++) { float v = r[(dd + t) & 63]; s += v*v; }
            rr[t] = rsqrtf(s * (1.f/DD) + EPS);
        }
        __syncthreads();

        // y = rmsnorm(out)*rms_w + h_input; store + BN partials
        int node = grp*4 + g;
        float* yrow = g_y + (size_t)node*(LL*DD);
#pragma unroll
        for (int j = 0; j < 9; j++) {
            int l = lbase + j;
            if (l < LL) {
                float v = ob[g*(LL*DD) + l*DD + d] * rr[g*LL + l] * rw + hrow[l*DD + d];
                yrow[l*DD + d] = v;
                bsum += v; bsq += v*v;
            }
        }
        __syncthreads();   // before next iteration overwrites hsm/gz/ob
    }
    atomicAdd(&g_bnsum[d], bsum);
    atomicAdd(&g_bnsq[d], bsq);
}

// ---------------- K5: BN apply + ReLU6 + L-aggregation + residual ----------------
__global__ void k5(const float* __restrict__ hs, const float* __restrict__ gamma,
                   const float* __restrict__ beta, const float* __restrict__ aggw,
                   const float* __restrict__ aggb, float* __restrict__ out) {
    int idx = blockIdx.x*256 + threadIdx.x;
    int d = idx & 63;
    float cnt = (float)(NN*LL);
    float mean = g_bnsum[d] / cnt;
    float var  = g_bnsq[d] / cnt - mean*mean;
    float is = rsqrtf(var + EPS);
    float ga = __ldg(&gamma[d]) * is;
    float be = __ldg(&beta[d]) - mean * ga;
    const float* yrow = g_y + (size_t)(idx >> 6)*(LL*DD);
    float s = __ldg(&aggb[0]);
#pragma unroll
    for (int l = 0; l < LL; l++) {
        float v = yrow[l*DD + d] * ga + be;
        v = fminf(fmaxf(v, 0.f), 6.f);
        s += v * __ldg(&aggw[l]);
    }
    out[idx] = s + hs[idx];
}

// ---------------- host ----------------
extern "C" void kernel_launch(void* const* d_in, const int* in_sizes, int n_in,
                              void* d_out, int out_size) {
    const float* hs     = (const float*)d_in[0];
    const float* hs_e   = (const float*)d_in[1];
    const float* degree = (const float*)d_in[2];
    const float* noise  = (const float*)d_in[3];
    const float* fc1w   = (const float*)d_in[4];
    const float* fc1b   = (const float*)d_in[5];
    const float* convw  = (const float*)d_in[6];
    const float* convb  = (const float*)d_in[7];
    const float* fc2w   = (const float*)d_in[8];
    const float* fc2b   = (const float*)d_in[9];
    const float* rmsw   = (const float*)d_in[10];
    const float* gamma  = (const float*)d_in[11];
    const float* beta   = (const float*)d_in[12];
    const float* aggw   = (const float*)d_in[13];
    const float* aggb   = (const float*)d_in[14];
    const int*   src    = (const int*)d_in[15];
    float* out = (float*)d_out;

    const int smem3 = (16384 + 8192 + 4*LL*DD + 4*LL*DIN + 4*LL*DD + 4*LL) * 4;
    cudaFuncSetAttribute(k3, cudaFuncAttributeMaxDynamicSharedMemorySize, smem3);

    kz<<<1, 64>>>();
    k1<<<NN/4, 256>>>(hs, hs_e, degree, noise);
    k2<<<NN, 256>>>(hs, src);
    k3<<<148, 512, smem3>>>(fc1w, fc1b, convw, convb, fc2w, fc2b, rmsw);
    k5<<<NN*DD/256, 256>>>(hs, gamma, beta, aggw, aggb, out);
}

// round 5
// speedup vs baseline: 1.1850x; 1.0278x over previous
#include <cuda_runtime.h>

#define NN 8192
#define DD 64
#define MAXDEG 16
#define KK 8
#define LL 17            // MAXDEG + 1
#define DIN 128          // D * EXPAND
#define EPS 1e-5f

// ---------------- device scratch (allocation-free) ----------------
__device__ float g_hflat[NN*MAXDEG*DD];   // sorted mailbox, flattened [N,1024]
__device__ float g_hinput[NN*LL*DD];      // [N,17,64]
__device__ float g_y[NN*LL*DD];           // [N,17,64]
__device__ float g_bnsum[DD];
__device__ float g_bnsq[DD];
__device__ float g_w1t[64*256];           // fc1_w transposed: [k][c]
__device__ float g_w2t[128*64];           // fc2_w transposed: [c][d]

__device__ __forceinline__ float sigm(float x) { return 1.f/(1.f+__expf(-x)); }

// ---------------- K0: zero BN accumulators (graph replays!) ----------------
__global__ void kz() {
    int t = threadIdx.x;
    if (t < DD) { g_bnsum[t] = 0.f; g_bnsq[t] = 0.f; }
}

// ---------------- KT: transpose weights into lane-coalesced layouts ----------------
__global__ void kt(const float* __restrict__ fc1w, const float* __restrict__ fc2w) {
    int i = blockIdx.x*256 + threadIdx.x;
    { int c = i >> 6, k = i & 63; g_w1t[k*256 + c] = fc1w[i]; }
    if (i < 64*128) { int d = i >> 7, c = i & 127; g_w2t[c*64 + d] = fc2w[i]; }
}

// ---------------- K1: message + mailbox rank-sort ----------------
__global__ void k1(const float* __restrict__ hs, const float* __restrict__ hs_e,
                   const float* __restrict__ degree, const float* __restrict__ noise) {
    int n = blockIdx.x*4 + (threadIdx.x >> 6);
    int d = threadIdx.x & 63;
    float h = hs[n*DD + d];
    float deg = __ldg(&degree[n]);
    float sc[KK];
#pragma unroll
    for (int k = 0; k < KK; k++) sc[k] = deg + __ldg(&noise[n*KK + k]);
#pragma unroll
    for (int k = 0; k < KK; k++) {
        float e = hs_e[(n*KK + k)*DD + d];
        float m = h * sigm(e);
        int r = 0;
#pragma unroll
        for (int j = 0; j < KK; j++)
            r += (sc[j] < sc[k]) || (sc[j] == sc[k] && j < k);   // stable rank
        g_hflat[n*(MAXDEG*DD) + r*DD + d] = m;
    }
#pragma unroll
    for (int j = KK; j < MAXDEG; j++)
        g_hflat[n*(MAXDEG*DD) + j*DD + d] = 0.f;
}

// ---------------- K2: (A+I) spmm gather + build h_input ----------------
__global__ void k2(const float* __restrict__ hs, const int* __restrict__ src) {
    int n = blockIdx.x;
    int t = threadIdx.x;
    if (t < DD) g_hinput[n*(LL*DD) + t] = hs[n*DD + t];   // slot 0 = hs
    float4 a = ((const float4*)(g_hflat + n*(MAXDEG*DD)))[t];
#pragma unroll
    for (int k = 0; k < KK; k++) {
        int s = __ldg(&src[n*KK + k]);
        float4 v = ((const float4*)(g_hflat + s*(MAXDEG*DD)))[t];
        a.x += v.x; a.y += v.y; a.z += v.z; a.w += v.w;
    }
    ((float4*)(g_hinput + n*(LL*DD) + DD))[t] = a;        // slots 1..16
}

// ---------------- K3: GatedCNN + RMSNorm + residual + BN partials ----------------
// 4096 blocks x 512 threads, 2 nodes/block, 256 threads/node, 2 CTAs/SM target.
// fc1: thread owns 1 channel x 17 rows. fc2: thread owns 1 channel x 4 rows (+1 epi).
__global__ void __launch_bounds__(512, 2)
k3(const float* __restrict__ fc1b, const float* __restrict__ convw,
   const float* __restrict__ convb, const float* __restrict__ fc2b,
   const float* __restrict__ rmsw) {
    __shared__ float hsm[2*LL*DD];       // 8704 B
    __shared__ float gz[2*LL*DIN];       // 17408 B
    __shared__ float ob[2*LL*DD];        // 8704 B
    __shared__ float rr[2*LL];
    __shared__ float ps[2*LL*8];         // rms partials
    __shared__ float bnred[2*DD];

    int t = threadIdx.x;
    int g = t >> 8;          // node in block (0/1)
    int u = t & 255;         // thread within node

    // stage 2 nodes' h_input
    {
        const float4* s4 = (const float4*)(g_hinput + (size_t)blockIdx.x*2*(LL*DD));
        float4* d4 = (float4*)hsm;
#pragma unroll
        for (int i = t; i < 2*LL*DD/4; i += 512) d4[i] = s4[i];
    }
    __syncthreads();

    const float* hrow = hsm + g*(LL*DD);

    // ---- fc1: channel c = u, all 17 rows ----
    float acc[LL];
#pragma unroll
    for (int l = 0; l < LL; l++) acc[l] = 0.f;
#pragma unroll 1
    for (int k4 = 0; k4 < 16; k4++) {
        float w0 = __ldg(&g_w1t[(k4*4+0)*256 + u]);
        float w1 = __ldg(&g_w1t[(k4*4+1)*256 + u]);
        float w2 = __ldg(&g_w1t[(k4*4+2)*256 + u]);
        float w3 = __ldg(&g_w1t[(k4*4+3)*256 + u]);
#pragma unroll
        for (int l = 0; l < LL; l++) {
            float4 h4 = *(const float4*)&hrow[l*DD + k4*4];
            acc[l] += h4.x*w0 + h4.y*w1 + h4.z*w2 + h4.w*w3;
        }
    }
    {
        float b1 = __ldg(&fc1b[u]);
#pragma unroll
        for (int l = 0; l < LL; l++) acc[l] += b1;
    }

    // z half (channels 128..255): silu(z) -> gz
    if (u >= 128) {
        float* zr = gz + g*(LL*DIN) + (u - 128);
#pragma unroll
        for (int l = 0; l < LL; l++) zr[l*DIN] = acc[l]*sigm(acc[l]);
    }
    __syncthreads();

    // x half (channels 0..127): causal depthwise conv + gate (in place)
    if (u < 128) {
        float cw0 = __ldg(&convw[u*4+0]), cw1 = __ldg(&convw[u*4+1]);
        float cw2 = __ldg(&convw[u*4+2]), cw3 = __ldg(&convw[u*4+3]);
        float cb  = __ldg(&convb[u]);
        float* xr = gz + g*(LL*DIN) + u;
#pragma unroll
        for (int l = 0; l < LL; l++) {
            float xc = cb + acc[l]*cw3;
            if (l >= 1) xc += acc[l-1]*cw2;
            if (l >= 2) xc += acc[l-2]*cw1;
            if (l >= 3) xc += acc[l-3]*cw0;
            xr[l*DIN] = xc*sigm(xc) * xr[l*DIN];
        }
    }
    __syncthreads();

    // ---- fc2: channel d = u&63, rows q*4..q*4+3; q==3 also does row 16 ----
    int d = u & 63;
    int q = u >> 6;
    int lbase = q*4;
    float acc2[4];
    float acce = 0.f;
#pragma unroll
    for (int j = 0; j < 4; j++) acc2[j] = 0.f;
    const float* grow = gz + g*(LL*DIN) + lbase*DIN;
    const float* erow = gz + g*(LL*DIN) + 16*DIN;
    bool has_epi = (q == 3);
#pragma unroll 1
    for (int c4 = 0; c4 < 32; c4++) {
        float wa = __ldg(&g_w2t[(c4*4+0)*64 + d]);
        float wb = __ldg(&g_w2t[(c4*4+1)*64 + d]);
        float wc = __ldg(&g_w2t[(c4*4+2)*64 + d]);
        float wd = __ldg(&g_w2t[(c4*4+3)*64 + d]);
#pragma unroll
        for (int j = 0; j < 4; j++) {
            float4 g4 = *(const float4*)&grow[j*DIN + c4*4];
            acc2[j] += g4.x*wa + g4.y*wb + g4.z*wc + g4.w*wd;
        }
        if (has_epi) {
            float4 g4 = *(const float4*)&erow[c4*4];
            acce += g4.x*wa + g4.y*wb + g4.z*wc + g4.w*wd;
        }
    }
    {
        float b2 = __ldg(&fc2b[d]);
#pragma unroll
        for (int j = 0; j < 4; j++)
            ob[g*(LL*DD) + (lbase+j)*DD + d] = acc2[j] + b2;
        if (has_epi) ob[g*(LL*DD) + 16*DD + d] = acce + b2;
    }
    __syncthreads();

    // rms partials: 34 rows x 8 threads each
    if (t < 2*LL*8) {
        int r = t >> 3, e = t & 7;                 // r: 0..33
        const float* row = ob + (r/LL)*(LL*DD) + (r%LL)*DD;
        float s = 0.f;
#pragma unroll
        for (int i = 0; i < 8; i++) { float v = row[e*8 + i]; s += v*v; }
        ps[t] = s;
    }
    __syncthreads();
    if (t < 2*LL) {
        float s = 0.f;
#pragma unroll
        for (int j = 0; j < 8; j++) s += ps[t*8 + j];
        rr[t] = rsqrtf(s * (1.f/DD) + EPS);
    }
    if (t < 2*DD) bnred[t] = 0.f;
    __syncthreads();

    // y = rmsnorm(out)*rms_w + h_input; store + BN partials
    {
        float rw = __ldg(&rmsw[d]);
        float bsum = 0.f, bsq = 0.f;
        int node = blockIdx.x*2 + g;
        float* yrow = g_y + (size_t)node*(LL*DD);
#pragma unroll
        for (int j = 0; j < 4; j++) {
            int l = lbase + j;
            float v = ob[g*(LL*DD) + l*DD + d] * rr[g*LL + l] * rw + hrow[l*DD + d];
            yrow[l*DD + d] = v;
            bsum += v; bsq += v*v;
        }
        if (has_epi) {
            float v = ob[g*(LL*DD) + 16*DD + d] * rr[g*LL + 16] * rw + hrow[16*DD + d];
            yrow[16*DD + d] = v;
            bsum += v; bsq += v*v;
        }
        atomicAdd(&bnred[d], bsum);
        atomicAdd(&bnred[DD + d], bsq);
    }
    __syncthreads();
    if (t < DD)            atomicAdd(&g_bnsum[t], bnred[t]);
    else if (t < 2*DD)     atomicAdd(&g_bnsq[t - DD], bnred[t]);
}

// ---------------- K5: BN apply + ReLU6 + L-aggregation + residual ----------------
__global__ void k5(const float* __restrict__ hs, const float* __restrict__ gamma,
                   const float* __restrict__ beta, const float* __restrict__ aggw,
                   const float* __restrict__ aggb, float* __restrict__ out) {
    int idx = blockIdx.x*256 + threadIdx.x;
    int d = idx & 63;
    float cnt = (float)(NN*LL);
    float mean = g_bnsum[d] / cnt;
    float var  = g_bnsq[d] / cnt - mean*mean;
    float is = rsqrtf(var + EPS);
    float ga = __ldg(&gamma[d]) * is;
    float be = __ldg(&beta[d]) - mean * ga;
    const float* yrow = g_y + (size_t)(idx >> 6)*(LL*DD);
    float s = __ldg(&aggb[0]);
#pragma unroll
    for (int l = 0; l < LL; l++) {
        float v = yrow[l*DD + d] * ga + be;
        v = fminf(fmaxf(v, 0.f), 6.f);
        s += v * __ldg(&aggw[l]);
    }
    out[idx] = s + hs[idx];
}

// ---------------- host ----------------
extern "C" void kernel_launch(void* const* d_in, const int* in_sizes, int n_in,
                              void* d_out, int out_size) {
    const float* hs     = (const float*)d_in[0];
    const float* hs_e   = (const float*)d_in[1];
    const float* degree = (const float*)d_in[2];
    const float* noise  = (const float*)d_in[3];
    const float* fc1w   = (const float*)d_in[4];
    const float* fc1b   = (const float*)d_in[5];
    const float* convw  = (const float*)d_in[6];
    const float* convb  = (const float*)d_in[7];
    const float* fc2w   = (const float*)d_in[8];
    const float* fc2b   = (const float*)d_in[9];
    const float* rmsw   = (const float*)d_in[10];
    const float* gamma  = (const float*)d_in[11];
    const float* beta   = (const float*)d_in[12];
    const float* aggw   = (const float*)d_in[13];
    const float* aggb   = (const float*)d_in[14];
    const int*   src    = (const int*)d_in[15];
    float* out = (float*)d_out;

    kz<<<1, 64>>>();
    kt<<<64, 256>>>(fc1w, fc2w);
    k1<<<NN/4, 256>>>(hs, hs_e, degree, noise);
    k2<<<NN, 256>>>(hs, src);
    k3<<<NN/2, 512>>>(fc1b, convw, convb, fc2b, rmsw);
    k5<<<NN*DD/256, 256>>>(hs, gamma, beta, aggw, aggb, out);
}